// round 4
// baseline (speedup 1.0000x reference)
#include <cuda_runtime.h>
#include <cstddef>

#define NN 8192
#define DD 512
#define SCALE 0.04419417382415922f   // 1/sqrt(512)

// ---------------- scratch (static __device__ — no allocs allowed) ----------
__device__ float g_q[NN * DD];
__device__ float g_k[NN * DD];
__device__ float g_v[NN * DD];
__device__ float g_sc_spill[(size_t)NN * NN / 8];     // 32 MB: score spill for deg>2048 rows
__device__ unsigned int g_adj[(size_t)NN * NN / 32];  // 8 MB adjacency bitmask
__device__ float g_vpart[64 * DD];
__device__ float g_vmean[DD];
__device__ int g_is64;

// ---------------- edge dtype detection -------------------------------------
__global__ void detect_kernel(const unsigned int* __restrict__ w) {
    __shared__ unsigned int red[256];
    unsigned int acc = 0;
    for (int i = threadIdx.x; i < 1024; i += 256) acc |= w[2 * i + 1];
    red[threadIdx.x] = acc;
    __syncthreads();
    #pragma unroll
    for (int s = 128; s > 0; s >>= 1) {
        if (threadIdx.x < s) red[threadIdx.x] |= red[threadIdx.x + s];
        __syncthreads();
    }
    if (threadIdx.x == 0) g_is64 = (red[0] == 0u) ? 1 : 0;
}

// ---------------- adjacency ------------------------------------------------
__global__ void adj_zero_kernel() {
    int i = blockIdx.x * blockDim.x + threadIdx.x;
    if (i < NN * (NN / 32)) g_adj[i] = 0u;
}

__global__ void adj_scatter_kernel(const void* __restrict__ ei, int E) {
    int e = blockIdx.x * blockDim.x + threadIdx.x;
    if (e >= E) return;
    int r, c;
    if (g_is64) {
        const long long* p = (const long long*)ei;
        r = (int)p[e];
        c = (int)p[(size_t)E + e];
    } else {
        const int* p = (const int*)ei;
        r = p[e];
        c = p[(size_t)E + e];
    }
    if ((unsigned)r >= NN || (unsigned)c >= NN) return;
    size_t bit = (size_t)r * NN + (size_t)c;
    atomicOr(&g_adj[bit >> 5], 1u << (bit & 31));
}

// ---------------- SGEMM: 128x128, BK=16, double-buffered, 8x8 microtile ----
__global__ __launch_bounds__(256, 2)
void sgemm_bias_kernel(const float* __restrict__ A,
                       const float* __restrict__ B,
                       const float* __restrict__ bias,
                       float* __restrict__ C,
                       int M, int Nc, int K)
{
    __shared__ __align__(16) float As[2][16][128];   // transposed: As[k][m]
    __shared__ __align__(16) float Bs[2][16][128];   // Bs[k][n]

    const int t  = threadIdx.x;
    const int tx = t & 15;
    const int ty = t >> 4;
    const int bm = blockIdx.y;
    const int bn = blockIdx.x;

    // loader indices: 2 float4 per thread per tile
    const int a_row0 = t >> 2;            // 0..63
    const int a_row1 = (t + 256) >> 2;    // 64..127
    const int a_k4   = (t & 3) * 4;       // 0,4,8,12
    const int b_row0 = t >> 5;            // 0..7
    const int b_row1 = ((t + 256) >> 5);  // 8..15
    const int b_col  = (t & 31) * 4;

    const float* Ag = &A[(size_t)(bm * 128) * K];
    const float* Bg = &B[(size_t)(bn * 128)];

    float acc[8][8];
    #pragma unroll
    for (int i = 0; i < 8; i++)
        #pragma unroll
        for (int j = 0; j < 8; j++) acc[i][j] = 0.0f;

    // prologue: load stage 0
    float4 av0 = *(const float4*)&Ag[(size_t)a_row0 * K + a_k4];
    float4 av1 = *(const float4*)&Ag[(size_t)a_row1 * K + a_k4];
    float4 bv0 = *(const float4*)&Bg[(size_t)b_row0 * Nc + b_col];
    float4 bv1 = *(const float4*)&Bg[(size_t)b_row1 * Nc + b_col];
    As[0][a_k4 + 0][a_row0] = av0.x;
    As[0][a_k4 + 1][a_row0] = av0.y;
    As[0][a_k4 + 2][a_row0] = av0.z;
    As[0][a_k4 + 3][a_row0] = av0.w;
    As[0][a_k4 + 0][a_row1] = av1.x;
    As[0][a_k4 + 1][a_row1] = av1.y;
    As[0][a_k4 + 2][a_row1] = av1.z;
    As[0][a_k4 + 3][a_row1] = av1.w;
    *(float4*)&Bs[0][b_row0][b_col] = bv0;
    *(float4*)&Bs[0][b_row1][b_col] = bv1;
    __syncthreads();

    int cur = 0;
    for (int kt = 16; kt <= K; kt += 16) {
        // prefetch next stage into registers (skipped on last iter)
        if (kt < K) {
            av0 = *(const float4*)&Ag[(size_t)a_row0 * K + kt + a_k4];
            av1 = *(const float4*)&Ag[(size_t)a_row1 * K + kt + a_k4];
            bv0 = *(const float4*)&Bg[(size_t)(kt + b_row0) * Nc + b_col];
            bv1 = *(const float4*)&Bg[(size_t)(kt + b_row1) * Nc + b_col];
        }

        // compute current stage
        #pragma unroll
        for (int kk = 0; kk < 16; kk++) {
            float4 a0 = *(const float4*)&As[cur][kk][ty * 4];
            float4 a1 = *(const float4*)&As[cur][kk][ty * 4 + 64];
            float4 b0 = *(const float4*)&Bs[cur][kk][tx * 4];
            float4 b1 = *(const float4*)&Bs[cur][kk][tx * 4 + 64];
            float a[8] = {a0.x, a0.y, a0.z, a0.w, a1.x, a1.y, a1.z, a1.w};
            float b[8] = {b0.x, b0.y, b0.z, b0.w, b1.x, b1.y, b1.z, b1.w};
            #pragma unroll
            for (int i = 0; i < 8; i++)
                #pragma unroll
                for (int j = 0; j < 8; j++)
                    acc[i][j] += a[i] * b[j];
        }

        // store next stage (other buffer — no barrier needed before stores)
        if (kt < K) {
            int nxt = cur ^ 1;
            As[nxt][a_k4 + 0][a_row0] = av0.x;
            As[nxt][a_k4 + 1][a_row0] = av0.y;
            As[nxt][a_k4 + 2][a_row0] = av0.z;
            As[nxt][a_k4 + 3][a_row0] = av0.w;
            As[nxt][a_k4 + 0][a_row1] = av1.x;
            As[nxt][a_k4 + 1][a_row1] = av1.y;
            As[nxt][a_k4 + 2][a_row1] = av1.z;
            As[nxt][a_k4 + 3][a_row1] = av1.w;
            *(float4*)&Bs[nxt][b_row0][b_col] = bv0;
            *(float4*)&Bs[nxt][b_row1][b_col] = bv1;
            __syncthreads();
            cur = nxt;
        }
    }

    // epilogue: vectorized bias add + store (two float4 per microtile row)
    #pragma unroll
    for (int i = 0; i < 8; i++) {
        int m = bm * 128 + ((i < 4) ? (ty * 4 + i) : (64 + ty * 4 + (i - 4)));
        int n0 = bn * 128 + tx * 4;
        float4 bb0 = *(const float4*)&bias[n0];
        float4 bb1 = *(const float4*)&bias[n0 + 64];
        float4 o0 = {acc[i][0] + bb0.x, acc[i][1] + bb0.y,
                     acc[i][2] + bb0.z, acc[i][3] + bb0.w};
        float4 o1 = {acc[i][4] + bb1.x, acc[i][5] + bb1.y,
                     acc[i][6] + bb1.z, acc[i][7] + bb1.w};
        *(float4*)&C[(size_t)m * Nc + n0]      = o0;
        *(float4*)&C[(size_t)m * Nc + n0 + 64] = o1;
    }
}

// ---------------- v column mean (for degree-0 rows), deterministic 2-stage -
__global__ void vmean1_kernel() {
    const int b = blockIdx.x;
    const int t = threadIdx.x;
    float s0 = 0.f, s1 = 0.f;
    for (int r = 0; r < 128; r++) {
        const float* v = &g_v[(size_t)(b * 128 + r) * DD];
        s0 += v[t];
        s1 += v[t + 256];
    }
    g_vpart[b * DD + t] = s0;
    g_vpart[b * DD + t + 256] = s1;
}

__global__ void vmean2_kernel() {
    const int t = threadIdx.x;
    float s0 = 0.f, s1 = 0.f;
    for (int b = 0; b < 64; b++) {
        s0 += g_vpart[b * DD + t];
        s1 += g_vpart[b * DD + t + 256];
    }
    g_vmean[t]       = s0 * (1.0f / NN);
    g_vmean[t + 256] = s1 * (1.0f / NN);
}

// ---------------- sparse attention: one block (256 thr) per row -----------
#define SC_CAP 2048

__global__ __launch_bounds__(256)
void spattn_kernel(float* __restrict__ out)
{
    const int i = blockIdx.x;
    const int t = threadIdx.x;
    const int lane = t & 31;
    const int wid  = t >> 5;

    __shared__ __align__(16) float qs[DD];
    __shared__ int   nbr[NN];
    __shared__ float sc[SC_CAP];
    __shared__ int   scan[256];
    __shared__ float red[256];

    for (int d = t; d < DD; d += 256) qs[d] = g_q[(size_t)i * DD + d];

    unsigned word = g_adj[i * 256 + t];
    int pc = __popc(word);
    scan[t] = pc;
    __syncthreads();
    #pragma unroll
    for (int off = 1; off < 256; off <<= 1) {
        int mine = scan[t];
        int add  = (t >= off) ? scan[t - off] : 0;
        __syncthreads();
        scan[t] = mine + add;
        __syncthreads();
    }
    const int deg = scan[255];
    {
        int base = scan[t] - pc;
        unsigned w = word;
        while (w) {
            int b = __ffs(w) - 1;
            w &= w - 1;
            nbr[base++] = t * 32 + b;
        }
    }
    __syncthreads();

    if (deg == 0) {
        for (int d = t; d < DD; d += 256)
            out[(size_t)i * DD + d] = g_vmean[d];
        return;
    }

    float* scores = (deg <= SC_CAP) ? sc : &g_sc_spill[(size_t)i * NN / 8];

    for (int s = wid; s < deg; s += 8) {
        const float* kj = &g_k[(size_t)nbr[s] * DD];
        float acc = 0.f;
        #pragma unroll 4
        for (int d = lane; d < DD; d += 32) acc += qs[d] * kj[d];
        #pragma unroll
        for (int o = 16; o > 0; o >>= 1) acc += __shfl_xor_sync(0xffffffffu, acc, o);
        if (lane == 0) scores[s] = acc * SCALE;
    }
    __syncthreads();

    float m = -3.4e38f;
    for (int s = t; s < deg; s += 256) m = fmaxf(m, scores[s]);
    red[t] = m;
    __syncthreads();
    #pragma unroll
    for (int s = 128; s > 0; s >>= 1) {
        if (t < s) red[t] = fmaxf(red[t], red[t + s]);
        __syncthreads();
    }
    m = red[0];
    __syncthreads();

    float sum = 0.f;
    for (int s = t; s < deg; s += 256) {
        float p = __expf(scores[s] - m);
        scores[s] = p;
        sum += p;
    }
    red[t] = sum;
    __syncthreads();
    #pragma unroll
    for (int s = 128; s > 0; s >>= 1) {
        if (t < s) red[t] += red[t + s];
        __syncthreads();
    }
    const float inv = 1.0f / red[0];
    __syncthreads();

    float o0 = 0.f, o1 = 0.f;
    for (int s = 0; s < deg; s++) {
        float p = scores[s];
        const float* vj = &g_v[(size_t)nbr[s] * DD];
        o0 += p * vj[t];
        o1 += p * vj[t + 256];
    }
    out[(size_t)i * DD + t]       = o0 * inv;
    out[(size_t)i * DD + t + 256] = o1 * inv;
}

// ---------------- launch ---------------------------------------------------
extern "C" void kernel_launch(void* const* d_in, const int* in_sizes, int n_in,
                              void* d_out, int out_size)
{
    const float* x  = (const float*)d_in[0];
    const void*  ei = d_in[1];
    const float* Wq = (const float*)d_in[2];
    const float* bq = (const float*)d_in[3];
    const float* Wk = (const float*)d_in[4];
    const float* bk = (const float*)d_in[5];
    const float* Wv = (const float*)d_in[6];
    const float* bv = (const float*)d_in[7];
    float* out = (float*)d_out;
    const int E = in_sizes[1] / 2;

    float *pq, *pk, *pv;
    cudaGetSymbolAddress((void**)&pq, g_q);
    cudaGetSymbolAddress((void**)&pk, g_k);
    cudaGetSymbolAddress((void**)&pv, g_v);

    detect_kernel<<<1, 256>>>((const unsigned int*)ei);
    adj_zero_kernel<<<(NN * (NN / 32) + 255) / 256, 256>>>();
    adj_scatter_kernel<<<(E + 255) / 256, 256>>>(ei, E);

    dim3 gProj(DD / 128, NN / 128);
    sgemm_bias_kernel<<<gProj, 256>>>(x, Wq, bq, pq, NN, DD, DD);
    sgemm_bias_kernel<<<gProj, 256>>>(x, Wk, bk, pk, NN, DD, DD);
    sgemm_bias_kernel<<<gProj, 256>>>(x, Wv, bv, pv, NN, DD, DD);

    vmean1_kernel<<<64, 256>>>();
    vmean2_kernel<<<1, 256>>>();

    spattn_kernel<<<NN, 256>>>(out);
}

// round 5
// speedup vs baseline: 1.1280x; 1.1280x over previous
#include <cuda_runtime.h>
#include <cstddef>
#include <cstdint>

#define NN 8192
#define DD 512
#define SCALE 0.04419417382415922f   // 1/sqrt(512)

// ---------------- scratch (static __device__ — no allocs allowed) ----------
__device__ float g_q[NN * DD];
__device__ float g_k[NN * DD];
__device__ float g_v[NN * DD];
__device__ float g_sc_spill[(size_t)NN * NN / 8];     // 32 MB: score spill for deg>2048 rows
__device__ unsigned int g_adj[(size_t)NN * NN / 32];  // 8 MB adjacency bitmask
__device__ float g_vpart[64 * DD];
__device__ float g_vmean[DD];
__device__ int g_is64;

// ---------------- edge dtype detection -------------------------------------
__global__ void detect_kernel(const unsigned int* __restrict__ w) {
    __shared__ unsigned int red[256];
    unsigned int acc = 0;
    for (int i = threadIdx.x; i < 1024; i += 256) acc |= w[2 * i + 1];
    red[threadIdx.x] = acc;
    __syncthreads();
    #pragma unroll
    for (int s = 128; s > 0; s >>= 1) {
        if (threadIdx.x < s) red[threadIdx.x] |= red[threadIdx.x + s];
        __syncthreads();
    }
    if (threadIdx.x == 0) g_is64 = (red[0] == 0u) ? 1 : 0;
}

// ---------------- adjacency ------------------------------------------------
__global__ void adj_zero_kernel() {
    int i = blockIdx.x * blockDim.x + threadIdx.x;
    if (i < NN * (NN / 32)) g_adj[i] = 0u;
}

__global__ void adj_scatter_kernel(const void* __restrict__ ei, int E) {
    int e = blockIdx.x * blockDim.x + threadIdx.x;
    if (e >= E) return;
    int r, c;
    if (g_is64) {
        const long long* p = (const long long*)ei;
        r = (int)p[e];
        c = (int)p[(size_t)E + e];
    } else {
        const int* p = (const int*)ei;
        r = p[e];
        c = p[(size_t)E + e];
    }
    if ((unsigned)r >= NN || (unsigned)c >= NN) return;
    size_t bit = (size_t)r * NN + (size_t)c;
    atomicOr(&g_adj[bit >> 5], 1u << (bit & 31));
}

// ---------------- tf32 helpers ---------------------------------------------
__device__ __forceinline__ uint32_t f2tf32(float x) {
    uint32_t r;
    asm("cvt.rna.tf32.f32 %0, %1;" : "=r"(r) : "f"(x));
    return r;
}

__device__ __forceinline__ void mma_tf32(float* d,
                                         uint32_t a0, uint32_t a1, uint32_t a2, uint32_t a3,
                                         uint32_t b0, uint32_t b1) {
    asm volatile(
        "mma.sync.aligned.m16n8k8.row.col.f32.tf32.tf32.f32 "
        "{%0,%1,%2,%3}, {%4,%5,%6,%7}, {%8,%9}, {%0,%1,%2,%3};\n"
        : "+f"(d[0]), "+f"(d[1]), "+f"(d[2]), "+f"(d[3])
        : "r"(a0), "r"(a1), "r"(a2), "r"(a3), "r"(b0), "r"(b1));
}

// ---------------- fused QKV projection: tf32 tensor cores, 2xTF32 split ----
// 128x128 C tile, BK=16, 256 threads = 8 warps (4 warpRows x 2 warpCols),
// warp tile 32x64. grid.z selects (Wq,bq,q)/(Wk,bk,k)/(Wv,bv,v).
#define LDA 20      // As row stride in words ([m][k] layout, conflict-free frag loads)
#define LDB 136     // Bs row stride in words ([k][n] layout, conflict-free frag loads)

__global__ __launch_bounds__(256, 2)
void proj_tf32_kernel(const float* __restrict__ x,
                      const float* __restrict__ W0, const float* __restrict__ bb0, float* __restrict__ o0,
                      const float* __restrict__ W1, const float* __restrict__ bb1, float* __restrict__ o1,
                      const float* __restrict__ W2, const float* __restrict__ bb2, float* __restrict__ o2)
{
    __shared__ uint32_t As_hi[128 * LDA];
    __shared__ uint32_t As_lo[128 * LDA];
    __shared__ uint32_t Bs_hi[16 * LDB];
    __shared__ uint32_t Bs_lo[16 * LDB];

    const float* W;
    const float* bias;
    float* C;
    if (blockIdx.z == 0)      { W = W0; bias = bb0; C = o0; }
    else if (blockIdx.z == 1) { W = W1; bias = bb1; C = o1; }
    else                      { W = W2; bias = bb2; C = o2; }

    const int t = threadIdx.x;
    const int lane = t & 31;
    const int wid  = t >> 5;
    const int warpRow = wid >> 1;       // 0..3
    const int warpCol = wid & 1;        // 0..1
    const int g  = lane >> 2;           // 0..7
    const int tg = lane & 3;            // 0..3
    const int bm = blockIdx.y;
    const int bn = blockIdx.x;

    // loader indices
    const int a_row = t >> 2;           // 0..63 (second: +64)
    const int a_k4  = (t & 3) * 4;      // 0,4,8,12
    const int b_k   = t >> 5;           // 0..7  (second: +8)
    const int b_c   = (t & 31) * 4;     // 0..124

    const float* Ag = x + (size_t)(bm * 128) * DD;
    const float* Bg = W + bn * 128;

    float d[2][8][4];
    #pragma unroll
    for (int mt = 0; mt < 2; mt++)
        #pragma unroll
        for (int nt = 0; nt < 8; nt++)
            #pragma unroll
            for (int r = 0; r < 4; r++) d[mt][nt][r] = 0.0f;

    // prologue loads (kt = 0)
    float4 av0 = *(const float4*)&Ag[(size_t)a_row * DD + a_k4];
    float4 av1 = *(const float4*)&Ag[(size_t)(a_row + 64) * DD + a_k4];
    float4 bv0 = *(const float4*)&Bg[(size_t)b_k * DD + b_c];
    float4 bv1 = *(const float4*)&Bg[(size_t)(b_k + 8) * DD + b_c];

    for (int kt = 0; kt < DD; kt += 16) {
        __syncthreads();   // previous stage fully consumed

        // store A with hi/lo split ([m][k], stride LDA)
        {
            const float a0v[4] = {av0.x, av0.y, av0.z, av0.w};
            const float a1v[4] = {av1.x, av1.y, av1.z, av1.w};
            #pragma unroll
            for (int j = 0; j < 4; j++) {
                uint32_t h = f2tf32(a0v[j]);
                As_hi[a_row * LDA + a_k4 + j] = h;
                As_lo[a_row * LDA + a_k4 + j] = f2tf32(a0v[j] - __uint_as_float(h));
                uint32_t h1 = f2tf32(a1v[j]);
                As_hi[(a_row + 64) * LDA + a_k4 + j] = h1;
                As_lo[(a_row + 64) * LDA + a_k4 + j] = f2tf32(a1v[j] - __uint_as_float(h1));
            }
        }
        // store B with hi/lo split ([k][n], stride LDB) — vectorized
        {
            uint4 h0, l0, h1, l1;
            h0.x = f2tf32(bv0.x); l0.x = f2tf32(bv0.x - __uint_as_float(h0.x));
            h0.y = f2tf32(bv0.y); l0.y = f2tf32(bv0.y - __uint_as_float(h0.y));
            h0.z = f2tf32(bv0.z); l0.z = f2tf32(bv0.z - __uint_as_float(h0.z));
            h0.w = f2tf32(bv0.w); l0.w = f2tf32(bv0.w - __uint_as_float(h0.w));
            h1.x = f2tf32(bv1.x); l1.x = f2tf32(bv1.x - __uint_as_float(h1.x));
            h1.y = f2tf32(bv1.y); l1.y = f2tf32(bv1.y - __uint_as_float(h1.y));
            h1.z = f2tf32(bv1.z); l1.z = f2tf32(bv1.z - __uint_as_float(h1.z));
            h1.w = f2tf32(bv1.w); l1.w = f2tf32(bv1.w - __uint_as_float(h1.w));
            *(uint4*)&Bs_hi[b_k * LDB + b_c]       = h0;
            *(uint4*)&Bs_lo[b_k * LDB + b_c]       = l0;
            *(uint4*)&Bs_hi[(b_k + 8) * LDB + b_c] = h1;
            *(uint4*)&Bs_lo[(b_k + 8) * LDB + b_c] = l1;
        }
        __syncthreads();

        // prefetch next stage (overlaps with compute below)
        if (kt + 16 < DD) {
            av0 = *(const float4*)&Ag[(size_t)a_row * DD + kt + 16 + a_k4];
            av1 = *(const float4*)&Ag[(size_t)(a_row + 64) * DD + kt + 16 + a_k4];
            bv0 = *(const float4*)&Bg[(size_t)(kt + 16 + b_k) * DD + b_c];
            bv1 = *(const float4*)&Bg[(size_t)(kt + 16 + b_k + 8) * DD + b_c];
        }

        // compute: two k8 steps
        #pragma unroll
        for (int ks = 0; ks < 2; ks++) {
            const int k0 = ks * 8;
            uint32_t ahi[2][4], alo[2][4];
            #pragma unroll
            for (int mt = 0; mt < 2; mt++) {
                const int mrow = warpRow * 32 + mt * 16;
                ahi[mt][0] = As_hi[(mrow + g) * LDA + k0 + tg];
                ahi[mt][1] = As_hi[(mrow + g + 8) * LDA + k0 + tg];
                ahi[mt][2] = As_hi[(mrow + g) * LDA + k0 + tg + 4];
                ahi[mt][3] = As_hi[(mrow + g + 8) * LDA + k0 + tg + 4];
                alo[mt][0] = As_lo[(mrow + g) * LDA + k0 + tg];
                alo[mt][1] = As_lo[(mrow + g + 8) * LDA + k0 + tg];
                alo[mt][2] = As_lo[(mrow + g) * LDA + k0 + tg + 4];
                alo[mt][3] = As_lo[(mrow + g + 8) * LDA + k0 + tg + 4];
            }
            #pragma unroll
            for (int nt = 0; nt < 8; nt++) {
                const int nb = warpCol * 64 + nt * 8;
                uint32_t bhi0 = Bs_hi[(k0 + tg) * LDB + nb + g];
                uint32_t bhi1 = Bs_hi[(k0 + tg + 4) * LDB + nb + g];
                uint32_t blo0 = Bs_lo[(k0 + tg) * LDB + nb + g];
                uint32_t blo1 = Bs_lo[(k0 + tg + 4) * LDB + nb + g];
                #pragma unroll
                for (int mt = 0; mt < 2; mt++) {
                    mma_tf32(d[mt][nt], ahi[mt][0], ahi[mt][1], ahi[mt][2], ahi[mt][3], bhi0, bhi1);
                    mma_tf32(d[mt][nt], ahi[mt][0], ahi[mt][1], ahi[mt][2], ahi[mt][3], blo0, blo1);
                    mma_tf32(d[mt][nt], alo[mt][0], alo[mt][1], alo[mt][2], alo[mt][3], bhi0, bhi1);
                }
            }
        }
    }

    // epilogue: bias + store (float2 per fragment row)
    #pragma unroll
    for (int mt = 0; mt < 2; mt++) {
        const int row = bm * 128 + warpRow * 32 + mt * 16 + g;
        #pragma unroll
        for (int nt = 0; nt < 8; nt++) {
            const int col = bn * 128 + warpCol * 64 + nt * 8 + 2 * tg;
            float2 bb = *(const float2*)&bias[col];
            float2 lo = {d[mt][nt][0] + bb.x, d[mt][nt][1] + bb.y};
            float2 hi = {d[mt][nt][2] + bb.x, d[mt][nt][3] + bb.y};
            *(float2*)&C[(size_t)row * DD + col]       = lo;
            *(float2*)&C[(size_t)(row + 8) * DD + col] = hi;
        }
    }
}

// ---------------- v column mean (for degree-0 rows), deterministic 2-stage -
__global__ void vmean1_kernel() {
    const int b = blockIdx.x;
    const int t = threadIdx.x;
    float s0 = 0.f, s1 = 0.f;
    for (int r = 0; r < 128; r++) {
        const float* v = &g_v[(size_t)(b * 128 + r) * DD];
        s0 += v[t];
        s1 += v[t + 256];
    }
    g_vpart[b * DD + t] = s0;
    g_vpart[b * DD + t + 256] = s1;
}

__global__ void vmean2_kernel() {
    const int t = threadIdx.x;
    float s0 = 0.f, s1 = 0.f;
    for (int b = 0; b < 64; b++) {
        s0 += g_vpart[b * DD + t];
        s1 += g_vpart[b * DD + t + 256];
    }
    g_vmean[t]       = s0 * (1.0f / NN);
    g_vmean[t + 256] = s1 * (1.0f / NN);
}

// ---------------- sparse attention: one block (256 thr) per row -----------
#define SC_CAP 2048

__global__ __launch_bounds__(256)
void spattn_kernel(float* __restrict__ out)
{
    const int i = blockIdx.x;
    const int t = threadIdx.x;
    const int lane = t & 31;
    const int wid  = t >> 5;

    __shared__ __align__(16) float qs[DD];
    __shared__ int   nbr[NN];
    __shared__ float sc[SC_CAP];
    __shared__ int   scan[256];
    __shared__ float red[256];

    for (int d = t; d < DD; d += 256) qs[d] = g_q[(size_t)i * DD + d];

    unsigned word = g_adj[i * 256 + t];
    int pc = __popc(word);
    scan[t] = pc;
    __syncthreads();
    #pragma unroll
    for (int off = 1; off < 256; off <<= 1) {
        int mine = scan[t];
        int add  = (t >= off) ? scan[t - off] : 0;
        __syncthreads();
        scan[t] = mine + add;
        __syncthreads();
    }
    const int deg = scan[255];
    {
        int base = scan[t] - pc;
        unsigned w = word;
        while (w) {
            int b = __ffs(w) - 1;
            w &= w - 1;
            nbr[base++] = t * 32 + b;
        }
    }
    __syncthreads();

    if (deg == 0) {
        for (int d = t; d < DD; d += 256)
            out[(size_t)i * DD + d] = g_vmean[d];
        return;
    }

    float* scores = (deg <= SC_CAP) ? sc : &g_sc_spill[(size_t)i * NN / 8];

    for (int s = wid; s < deg; s += 8) {
        const float* kj = &g_k[(size_t)nbr[s] * DD];
        float acc = 0.f;
        #pragma unroll 4
        for (int d = lane; d < DD; d += 32) acc += qs[d] * kj[d];
        #pragma unroll
        for (int o = 16; o > 0; o >>= 1) acc += __shfl_xor_sync(0xffffffffu, acc, o);
        if (lane == 0) scores[s] = acc * SCALE;
    }
    __syncthreads();

    float m = -3.4e38f;
    for (int s = t; s < deg; s += 256) m = fmaxf(m, scores[s]);
    red[t] = m;
    __syncthreads();
    #pragma unroll
    for (int s = 128; s > 0; s >>= 1) {
        if (t < s) red[t] = fmaxf(red[t], red[t + s]);
        __syncthreads();
    }
    m = red[0];
    __syncthreads();

    float sum = 0.f;
    for (int s = t; s < deg; s += 256) {
        float p = __expf(scores[s] - m);
        scores[s] = p;
        sum += p;
    }
    red[t] = sum;
    __syncthreads();
    #pragma unroll
    for (int s = 128; s > 0; s >>= 1) {
        if (t < s) red[t] += red[t + s];
        __syncthreads();
    }
    const float inv = 1.0f / red[0];
    __syncthreads();

    float o0 = 0.f, o1 = 0.f;
    for (int s = 0; s < deg; s++) {
        float p = scores[s];
        const float* vj = &g_v[(size_t)nbr[s] * DD];
        o0 += p * vj[t];
        o1 += p * vj[t + 256];
    }
    out[(size_t)i * DD + t]       = o0 * inv;
    out[(size_t)i * DD + t + 256] = o1 * inv;
}

// ---------------- launch ---------------------------------------------------
extern "C" void kernel_launch(void* const* d_in, const int* in_sizes, int n_in,
                              void* d_out, int out_size)
{
    const float* x  = (const float*)d_in[0];
    const void*  ei = d_in[1];
    const float* Wq = (const float*)d_in[2];
    const float* bq = (const float*)d_in[3];
    const float* Wk = (const float*)d_in[4];
    const float* bk = (const float*)d_in[5];
    const float* Wv = (const float*)d_in[6];
    const float* bv = (const float*)d_in[7];
    float* out = (float*)d_out;
    const int E = in_sizes[1] / 2;

    float *pq, *pk, *pv;
    cudaGetSymbolAddress((void**)&pq, g_q);
    cudaGetSymbolAddress((void**)&pk, g_k);
    cudaGetSymbolAddress((void**)&pv, g_v);

    detect_kernel<<<1, 256>>>((const unsigned int*)ei);
    adj_zero_kernel<<<(NN * (NN / 32) + 255) / 256, 256>>>();
    adj_scatter_kernel<<<(E + 255) / 256, 256>>>(ei, E);

    // fused QKV projections on tensor cores (grid.z = 3)
    dim3 gProj(DD / 128, NN / 128, 3);
    proj_tf32_kernel<<<gProj, 256>>>(x, Wq, bq, pq, Wk, bk, pk, Wv, bv, pv);

    vmean1_kernel<<<64, 256>>>();
    vmean2_kernel<<<1, 256>>>();

    spattn_kernel<<<NN, 256>>>(out);
}